// round 1
// baseline (speedup 1.0000x reference)
#include <cuda_runtime.h>
#include <math.h>

// Problem constants (fixed shapes from reference)
#define B_  32
#define T_  1024
#define D_  1024
#define U_  1024
#define M_  (B_ * T_)     // 32768
#define N_  (4 * U_)      // 4096
#define K_  D_            // 1024

// Scratch for g = x @ W + b : [M, 4U] fp32 = 512 MB (device global, no alloc)
__device__ float g_scratch[(size_t)M_ * N_];

// ---------------------------------------------------------------------------
// SGEMM: C[M,N] = A[M,K] @ W[K,N] + bias[N]
// 128x128 block tile, BK=8, 256 threads, 8x8 register micro-tile.
// ---------------------------------------------------------------------------
#define BM 128
#define BN 128
#define BK 8
#define TM 8
#define TN 8

__global__ __launch_bounds__(256, 2)
void sru_gemm_kernel(const float* __restrict__ A,
                     const float* __restrict__ W,
                     const float* __restrict__ bias) {
    const int cRow = blockIdx.y;   // M tile
    const int cCol = blockIdx.x;   // N tile

    __shared__ float As[BK][BM];   // A tile transposed for broadcast loads
    __shared__ float Bs[BK][BN];

    const int tid = threadIdx.x;
    const int threadCol = tid % (BN / TN);   // 0..15
    const int threadRow = tid / (BN / TN);   // 0..15

    // Global-load mapping
    const int innerRowA = tid >> 1;          // 0..127
    const int innerColA = (tid & 1) * 4;     // 0 or 4
    const int innerRowB = tid >> 5;          // 0..7
    const int innerColB = (tid & 31) * 4;    // 0..124

    const float* Ag = A + (size_t)cRow * BM * K_;
    const float* Bg = W + (size_t)cCol * BN;

    float acc[TM][TN];
    #pragma unroll
    for (int i = 0; i < TM; i++)
        #pragma unroll
        for (int j = 0; j < TN; j++)
            acc[i][j] = 0.0f;

    float regM[TM], regN[TN];

    for (int k0 = 0; k0 < K_; k0 += BK) {
        // Load A tile (128 x 8) -> As transposed
        float4 a4 = *reinterpret_cast<const float4*>(
            Ag + (size_t)innerRowA * K_ + k0 + innerColA);
        As[innerColA + 0][innerRowA] = a4.x;
        As[innerColA + 1][innerRowA] = a4.y;
        As[innerColA + 2][innerRowA] = a4.z;
        As[innerColA + 3][innerRowA] = a4.w;

        // Load B tile (8 x 128)
        *reinterpret_cast<float4*>(&Bs[innerRowB][innerColB]) =
            *reinterpret_cast<const float4*>(
                Bg + (size_t)(k0 + innerRowB) * N_ + innerColB);

        __syncthreads();

        #pragma unroll
        for (int k = 0; k < BK; k++) {
            #pragma unroll
            for (int i = 0; i < TM; i++) regM[i] = As[k][threadRow * TM + i];
            #pragma unroll
            for (int j = 0; j < TN; j++) regN[j] = Bs[k][threadCol * TN + j];
            #pragma unroll
            for (int i = 0; i < TM; i++)
                #pragma unroll
                for (int j = 0; j < TN; j++)
                    acc[i][j] = fmaf(regM[i], regN[j], acc[i][j]);
        }
        __syncthreads();
    }

    // Epilogue: add bias, store to g_scratch
    #pragma unroll
    for (int i = 0; i < TM; i++) {
        const size_t row = (size_t)cRow * BM + threadRow * TM + i;
        #pragma unroll
        for (int j = 0; j < TN; j += 4) {
            const int col = cCol * BN + threadCol * TN + j;
            float4 v;
            v.x = acc[i][j + 0] + bias[col + 0];
            v.y = acc[i][j + 1] + bias[col + 1];
            v.z = acc[i][j + 2] + bias[col + 2];
            v.w = acc[i][j + 3] + bias[col + 3];
            *reinterpret_cast<float4*>(&g_scratch[row * N_ + col]) = v;
        }
    }
}

// ---------------------------------------------------------------------------
// Sequential SRU scan over T. One thread per (b, u) lane.
//   f = sigmoid(a1 + Vf*c_prev); c = f*c_prev + (1-f)*a2
//   r = sigmoid(a3 + Vr*c_prev); h = r*c + (1-r)*a4
// g layout: [B*T, 4U], columns [0,U)=a1, [U,2U)=a2, [2U,3U)=a3, [3U,4U)=a4
// ---------------------------------------------------------------------------
__global__ __launch_bounds__(256)
void sru_scan_kernel(const float* __restrict__ c0,
                     const float* __restrict__ Vr,
                     const float* __restrict__ Vf,
                     float* __restrict__ out) {
    const int idx = blockIdx.x * blockDim.x + threadIdx.x;  // 0 .. B*U-1
    if (idx >= B_ * U_) return;
    const int b = idx / U_;
    const int u = idx - b * U_;

    float c = c0[idx];
    const float vr = Vr[u];
    const float vf = Vf[u];

    const float* gb = g_scratch + (size_t)b * T_ * N_ + u;
    float* ob = out + (size_t)b * T_ * U_ + u;

    for (int t = 0; t < T_; t++) {
        const float* gt = gb + (size_t)t * N_;
        const float a1 = gt[0];
        const float a2 = gt[U_];
        const float a3 = gt[2 * U_];
        const float a4 = gt[3 * U_];

        const float f = 1.0f / (1.0f + expf(-(a1 + vf * c)));
        const float cn = f * c + (1.0f - f) * a2;
        const float r = 1.0f / (1.0f + expf(-(a3 + vr * c)));
        const float h = r * cn + (1.0f - r) * a4;

        c = cn;
        ob[(size_t)t * U_] = h;
    }
}

// ---------------------------------------------------------------------------
// Launch: inputs in metadata order: x, h0, c0, W, b, Vr, Vf
// ---------------------------------------------------------------------------
extern "C" void kernel_launch(void* const* d_in, const int* in_sizes, int n_in,
                              void* d_out, int out_size) {
    const float* x  = (const float*)d_in[0];
    // d_in[1] = h0 (unused by reference)
    const float* c0 = (const float*)d_in[2];
    const float* W  = (const float*)d_in[3];
    const float* b  = (const float*)d_in[4];
    const float* Vr = (const float*)d_in[5];
    const float* Vf = (const float*)d_in[6];
    float* out = (float*)d_out;

    dim3 gemmGrid(N_ / BN, M_ / BM);   // (32, 256)
    sru_gemm_kernel<<<gemmGrid, 256>>>(x, W, b);

    const int lanes = B_ * U_;         // 32768
    sru_scan_kernel<<<(lanes + 255) / 256, 256>>>(c0, Vr, Vf, out);
}

// round 3
// speedup vs baseline: 1.9404x; 1.9404x over previous
#include <cuda_runtime.h>
#include <cuda_bf16.h>
#include <math.h>
#include <stdint.h>

// ---------------------------------------------------------------------------
// Problem constants
// ---------------------------------------------------------------------------
#define B_  32
#define T_  1024
#define D_  1024
#define U_  1024
#define M_  (B_ * T_)     // 32768
#define N_  (4 * U_)      // 4096
#define K_  D_            // 1024

// Device scratch (allocation-free rule: __device__ globals)
__device__ float g_scratch[(size_t)M_ * N_];                       // 512 MB
__device__ __align__(16) __nv_bfloat16 A_hi_g[(size_t)M_ * K_];    // 64 MB
__device__ __align__(16) __nv_bfloat16 A_lo_g[(size_t)M_ * K_];    // 64 MB
__device__ __align__(16) __nv_bfloat16 Wt_hi_g[(size_t)N_ * K_];   // 8 MB
__device__ __align__(16) __nv_bfloat16 Wt_lo_g[(size_t)N_ * K_];   // 8 MB

// ---------------------------------------------------------------------------
// PTX helpers (all base-target instructions: sm_80/sm_90, no arch gating)
// ---------------------------------------------------------------------------
__device__ __forceinline__ uint32_t smem_u32(const void* p) {
    uint32_t a;
    asm("{ .reg .u64 t; cvta.to.shared.u64 t, %1; cvt.u32.u64 %0, t; }" : "=r"(a) : "l"(p));
    return a;
}
__device__ __forceinline__ void cp_async16(uint32_t dst, const void* src) {
    asm volatile("cp.async.cg.shared.global [%0], [%1], 16;" :: "r"(dst), "l"(src));
}
__device__ __forceinline__ void cp_commit() {
    asm volatile("cp.async.commit_group;");
}
template <int N>
__device__ __forceinline__ void cp_wait() {
    asm volatile("cp.async.wait_group %0;" :: "n"(N));
}
__device__ __forceinline__ void ldsm_x4(uint32_t* r, uint32_t addr) {
    asm volatile("ldmatrix.sync.aligned.m8n8.x4.shared.b16 {%0,%1,%2,%3}, [%4];"
                 : "=r"(r[0]), "=r"(r[1]), "=r"(r[2]), "=r"(r[3]) : "r"(addr));
}
__device__ __forceinline__ void mma_16816(float* d, const uint32_t* a,
                                          uint32_t b0, uint32_t b1) {
    asm volatile("mma.sync.aligned.m16n8k16.row.col.f32.bf16.bf16.f32 "
                 "{%0,%1,%2,%3}, {%4,%5,%6,%7}, {%8,%9}, {%0,%1,%2,%3};"
                 : "+f"(d[0]), "+f"(d[1]), "+f"(d[2]), "+f"(d[3])
                 : "r"(a[0]), "r"(a[1]), "r"(a[2]), "r"(a[3]), "r"(b0), "r"(b1));
}

// ---------------------------------------------------------------------------
// Prep 1: split x (fp32 [M,K]) into bf16 hi/lo
// ---------------------------------------------------------------------------
__global__ __launch_bounds__(256)
void split_x_kernel(const float* __restrict__ x) {
    size_t i = ((size_t)blockIdx.x * blockDim.x + threadIdx.x) * 4;
    float4 v = *reinterpret_cast<const float4*>(x + i);
    __nv_bfloat16 h0 = __float2bfloat16(v.x);
    __nv_bfloat16 h1 = __float2bfloat16(v.y);
    __nv_bfloat16 h2 = __float2bfloat16(v.z);
    __nv_bfloat16 h3 = __float2bfloat16(v.w);
    __nv_bfloat16 l0 = __float2bfloat16(v.x - __bfloat162float(h0));
    __nv_bfloat16 l1 = __float2bfloat16(v.y - __bfloat162float(h1));
    __nv_bfloat16 l2 = __float2bfloat16(v.z - __bfloat162float(h2));
    __nv_bfloat16 l3 = __float2bfloat16(v.w - __bfloat162float(h3));
    __nv_bfloat162* ph = reinterpret_cast<__nv_bfloat162*>(A_hi_g + i);
    __nv_bfloat162* pl = reinterpret_cast<__nv_bfloat162*>(A_lo_g + i);
    ph[0] = __nv_bfloat162(h0, h1);
    ph[1] = __nv_bfloat162(h2, h3);
    pl[0] = __nv_bfloat162(l0, l1);
    pl[1] = __nv_bfloat162(l2, l3);
}

// ---------------------------------------------------------------------------
// Prep 2: transpose W [K,N] -> Wt [N,K] with bf16 hi/lo split
// ---------------------------------------------------------------------------
__global__ __launch_bounds__(1024)
void transpose_w_kernel(const float* __restrict__ W) {
    __shared__ float tile[32][33];
    const int n0 = blockIdx.x * 32;
    const int k0 = blockIdx.y * 32;
    const int tx = threadIdx.x, ty = threadIdx.y;
    tile[ty][tx] = W[(size_t)(k0 + ty) * N_ + (n0 + tx)];
    __syncthreads();
    const float v = tile[tx][ty];  // = W[k0+tx][n0+ty]
    __nv_bfloat16 hi = __float2bfloat16(v);
    __nv_bfloat16 lo = __float2bfloat16(v - __bfloat162float(hi));
    const size_t o = (size_t)(n0 + ty) * K_ + (k0 + tx);
    Wt_hi_g[o] = hi;
    Wt_lo_g[o] = lo;
}

// ---------------------------------------------------------------------------
// HMMA GEMM: g[M,N] = A[M,K] @ Wt[N,K]^T + bias   (hi*hi + hi*lo + lo*hi)
// BM=128, BN=256, BK=32, 256 threads (8 warps: 2 along M x 4 along N,
// 64x64 warp tiles), 3-stage cp.async pipeline, mma.sync.m16n8k16 bf16.
// ---------------------------------------------------------------------------
#define BM 128
#define BN 256
#define BKQ 32
#define KPAD 40                    // padded smem row (elems) -> 80B rows
#define NSTAGE 3
#define NITER (K_ / BKQ)           // 32

// smem stage layout (bytes): Ahi[128*40], Alo, Bhi[256*40], Blo
#define SA_HI 0
#define SA_LO (BM * KPAD * 2)                  // 10240
#define SB_HI (2 * BM * KPAD * 2)              // 20480
#define SB_LO (2 * BM * KPAD * 2 + BN * KPAD * 2)  // 40960
#define STAGE_BYTES (2 * BM * KPAD * 2 + 2 * BN * KPAD * 2)  // 61440
#define GEMM_SMEM (NSTAGE * STAGE_BYTES)       // 184320

__global__ __launch_bounds__(256, 1)
void sru_gemm_mma_kernel(const __nv_bfloat16* __restrict__ Ahi,
                         const __nv_bfloat16* __restrict__ Alo,
                         const __nv_bfloat16* __restrict__ Bhi,
                         const __nv_bfloat16* __restrict__ Blo,
                         const float* __restrict__ bias) {
    extern __shared__ char smem[];
    const uint32_t sb = smem_u32(smem);
    const int tid = threadIdx.x;
    const int lane = tid & 31;
    const int wid = tid >> 5;
    const int wm = wid & 1;        // 0..1  (M warps)
    const int wn = wid >> 1;       // 0..3  (N warps)
    const int m_blk = blockIdx.y * BM;
    const int n_blk = blockIdx.x * BN;

    float acc[4][8][4];
    #pragma unroll
    for (int i = 0; i < 4; i++)
        #pragma unroll
        for (int j = 0; j < 8; j++)
            #pragma unroll
            for (int r = 0; r < 4; r++)
                acc[i][j][r] = 0.0f;

    // ---- stage loader (12 cp.async of 16B per thread) ----
    auto load_stage = [&](int s, int k0) {
        const uint32_t st = sb + s * STAGE_BYTES;
        #pragma unroll
        for (int i = 0; i < 2; i++) {              // A: 512 chunks per buffer
            const int ch = tid * 2 + i;
            const int r = ch >> 2, c = ch & 3;
            const size_t g = (size_t)(m_blk + r) * K_ + k0 + c * 8;
            const uint32_t so = (uint32_t)(r * KPAD + c * 8) * 2;
            cp_async16(st + SA_HI + so, Ahi + g);
            cp_async16(st + SA_LO + so, Alo + g);
        }
        #pragma unroll
        for (int i = 0; i < 4; i++) {              // B: 1024 chunks per buffer
            const int ch = tid * 4 + i;
            const int r = ch >> 2, c = ch & 3;
            const size_t g = (size_t)(n_blk + r) * K_ + k0 + c * 8;
            const uint32_t so = (uint32_t)(r * KPAD + c * 8) * 2;
            cp_async16(st + SB_HI + so, Bhi + g);
            cp_async16(st + SB_LO + so, Blo + g);
        }
    };

    // prologue: stages 0,1
    load_stage(0, 0);
    cp_commit();
    load_stage(1, BKQ);
    cp_commit();

    for (int it = 0; it < NITER; it++) {
        cp_wait<1>();
        __syncthreads();

        const uint32_t st = sb + (it % NSTAGE) * STAGE_BYTES;
        #pragma unroll
        for (int ks = 0; ks < 2; ks++) {
            // ---- A fragments (hi & lo), 4 m-tiles of 16 ----
            uint32_t aHi[4][4], aLo[4][4];
            const int arow = wm * 64 + (lane & 15);
            const int acol = ks * 16 + (lane >> 4) * 8;
            #pragma unroll
            for (int mt = 0; mt < 4; mt++) {
                const uint32_t off = (uint32_t)((arow + mt * 16) * KPAD + acol) * 2;
                ldsm_x4(aHi[mt], st + SA_HI + off);
                ldsm_x4(aLo[mt], st + SA_LO + off);
            }
            // ---- B fragments per n16 group, fused with mma ----
            const int brow = wn * 64 + (lane & 15);
            #pragma unroll
            for (int nt2 = 0; nt2 < 4; nt2++) {
                const uint32_t off = (uint32_t)((brow + nt2 * 16) * KPAD + acol) * 2;
                uint32_t bh[4], bl[4];
                ldsm_x4(bh, st + SB_HI + off);
                ldsm_x4(bl, st + SB_LO + off);
                #pragma unroll
                for (int mt = 0; mt < 4; mt++) {
                    float* e = acc[mt][2 * nt2];
                    mma_16816(e, aHi[mt], bh[0], bh[2]);
                    mma_16816(e, aHi[mt], bl[0], bl[2]);
                    mma_16816(e, aLo[mt], bh[0], bh[2]);
                    float* o = acc[mt][2 * nt2 + 1];
                    mma_16816(o, aHi[mt], bh[1], bh[3]);
                    mma_16816(o, aHi[mt], bl[1], bl[3]);
                    mma_16816(o, aLo[mt], bh[1], bh[3]);
                }
            }
        }
        __syncthreads();
        if (it + 2 < NITER) load_stage((it + 2) % NSTAGE, (it + 2) * BKQ);
        cp_commit();
    }

    // ---- epilogue: bias + store fp32 ----
    #pragma unroll
    for (int nt = 0; nt < 8; nt++) {
        const int col = n_blk + wn * 64 + nt * 8 + (lane & 3) * 2;
        const float bx = __ldg(&bias[col]);
        const float by = __ldg(&bias[col + 1]);
        #pragma unroll
        for (int mt = 0; mt < 4; mt++) {
            const int row = m_blk + wm * 64 + mt * 16 + (lane >> 2);
            float2 v0 = make_float2(acc[mt][nt][0] + bx, acc[mt][nt][1] + by);
            float2 v1 = make_float2(acc[mt][nt][2] + bx, acc[mt][nt][3] + by);
            *reinterpret_cast<float2*>(&g_scratch[(size_t)row * N_ + col]) = v0;
            *reinterpret_cast<float2*>(&g_scratch[(size_t)(row + 8) * N_ + col]) = v1;
        }
    }
}

// ---------------------------------------------------------------------------
// Sequential SRU scan, unrolled by 8 with hoisted loads (MLP=32 per thread)
// ---------------------------------------------------------------------------
__global__ __launch_bounds__(256)
void sru_scan_kernel(const float* __restrict__ c0,
                     const float* __restrict__ Vr,
                     const float* __restrict__ Vf,
                     float* __restrict__ out) {
    const int idx = blockIdx.x * blockDim.x + threadIdx.x;
    if (idx >= B_ * U_) return;
    const int b = idx / U_;
    const int u = idx - b * U_;

    float c = c0[idx];
    const float vr = Vr[u];
    const float vf = Vf[u];

    const float* gb = g_scratch + (size_t)b * T_ * N_ + u;
    float* ob = out + (size_t)b * T_ * U_ + u;

    for (int t0 = 0; t0 < T_; t0 += 8) {
        float a1[8], a2[8], a3[8], a4[8];
        #pragma unroll
        for (int j = 0; j < 8; j++) {
            const float* gt = gb + (size_t)(t0 + j) * N_;
            a1[j] = __ldcs(gt);
            a2[j] = __ldcs(gt + U_);
            a3[j] = __ldcs(gt + 2 * U_);
            a4[j] = __ldcs(gt + 3 * U_);
        }
        #pragma unroll
        for (int j = 0; j < 8; j++) {
            const float f = 1.0f / (1.0f + __expf(-(a1[j] + vf * c)));
            const float cn = f * c + (1.0f - f) * a2[j];
            const float r = 1.0f / (1.0f + __expf(-(a3[j] + vr * c)));
            const float h = r * cn + (1.0f - r) * a4[j];
            c = cn;
            ob[(size_t)(t0 + j) * U_] = h;
        }
    }
}

// ---------------------------------------------------------------------------
// Host launch.  Inputs: x, h0, c0, W, b, Vr, Vf
// ---------------------------------------------------------------------------
extern "C" void kernel_launch(void* const* d_in, const int* in_sizes, int n_in,
                              void* d_out, int out_size) {
    const float* x  = (const float*)d_in[0];
    // d_in[1] = h0 (unused by reference)
    const float* c0 = (const float*)d_in[2];
    const float* W  = (const float*)d_in[3];
    const float* b  = (const float*)d_in[4];
    const float* Vr = (const float*)d_in[5];
    const float* Vf = (const float*)d_in[6];
    float* out = (float*)d_out;

    void *pAhi, *pAlo, *pBhi, *pBlo;
    cudaGetSymbolAddress(&pAhi, A_hi_g);
    cudaGetSymbolAddress(&pAlo, A_lo_g);
    cudaGetSymbolAddress(&pBhi, Wt_hi_g);
    cudaGetSymbolAddress(&pBlo, Wt_lo_g);

    // Prep: split x, transpose+split W
    split_x_kernel<<<(int)((size_t)M_ * K_ / 4 / 256), 256>>>(x);
    transpose_w_kernel<<<dim3(N_ / 32, K_ / 32), dim3(32, 32)>>>(W);

    // HMMA GEMM
    static bool attr_set = false;
    if (!attr_set) {
        cudaFuncSetAttribute(sru_gemm_mma_kernel,
                             cudaFuncAttributeMaxDynamicSharedMemorySize, GEMM_SMEM);
        attr_set = true;
    }
    dim3 gg(N_ / BN, M_ / BM);  // (16, 256)
    sru_gemm_mma_kernel<<<gg, 256, GEMM_SMEM>>>(
        (const __nv_bfloat16*)pAhi, (const __nv_bfloat16*)pAlo,
        (const __nv_bfloat16*)pBhi, (const __nv_bfloat16*)pBlo, b);

    // Scan
    const int lanes = B_ * U_;
    sru_scan_kernel<<<(lanes + 255) / 256, 256>>>(c0, Vr, Vf, out);
}

// round 4
// speedup vs baseline: 3.2126x; 1.6556x over previous
#include <cuda_runtime.h>
#include <cuda_fp16.h>
#include <math.h>
#include <stdint.h>

// ---------------------------------------------------------------------------
// Problem constants
// ---------------------------------------------------------------------------
#define B_  32
#define T_  1024
#define D_  1024
#define U_  1024
#define M_  (B_ * T_)     // 32768
#define N_  (4 * U_)      // 4096
#define K_  D_            // 1024

// Device scratch (allocation-free rule: __device__ globals)
__device__ float g_scratch[(size_t)M_ * N_];                      // 512 MB
__device__ __align__(16) __half A_h_g[(size_t)M_ * K_];           // 64 MB
__device__ __align__(16) __half Wt_hi_g[(size_t)N_ * K_];         // 8 MB (64*W hi)
__device__ __align__(16) __half Wt_lo_g[(size_t)N_ * K_];         // 8 MB (64*W lo)

// ---------------------------------------------------------------------------
// PTX helpers (base-target instructions only: sm_80-level, no arch gating)
// ---------------------------------------------------------------------------
__device__ __forceinline__ uint32_t smem_u32(const void* p) {
    uint32_t a;
    asm("{ .reg .u64 t; cvta.to.shared.u64 t, %1; cvt.u32.u64 %0, t; }" : "=r"(a) : "l"(p));
    return a;
}
__device__ __forceinline__ void cp_async16(uint32_t dst, const void* src) {
    asm volatile("cp.async.cg.shared.global [%0], [%1], 16;" :: "r"(dst), "l"(src));
}
__device__ __forceinline__ void cp_commit() {
    asm volatile("cp.async.commit_group;");
}
template <int N>
__device__ __forceinline__ void cp_wait() {
    asm volatile("cp.async.wait_group %0;" :: "n"(N));
}
__device__ __forceinline__ void ldsm_x4(uint32_t* r, uint32_t addr) {
    asm volatile("ldmatrix.sync.aligned.m8n8.x4.shared.b16 {%0,%1,%2,%3}, [%4];"
                 : "=r"(r[0]), "=r"(r[1]), "=r"(r[2]), "=r"(r[3]) : "r"(addr));
}
__device__ __forceinline__ void mma_16816_f16(float* d, const uint32_t* a,
                                              uint32_t b0, uint32_t b1) {
    asm volatile("mma.sync.aligned.m16n8k16.row.col.f32.f16.f16.f32 "
                 "{%0,%1,%2,%3}, {%4,%5,%6,%7}, {%8,%9}, {%0,%1,%2,%3};"
                 : "+f"(d[0]), "+f"(d[1]), "+f"(d[2]), "+f"(d[3])
                 : "r"(a[0]), "r"(a[1]), "r"(a[2]), "r"(a[3]), "r"(b0), "r"(b1));
}

// ---------------------------------------------------------------------------
// Prep 1: round x (fp32 [M,K]) to fp16
// ---------------------------------------------------------------------------
__global__ __launch_bounds__(256)
void split_x_kernel(const float* __restrict__ x) {
    size_t i = ((size_t)blockIdx.x * blockDim.x + threadIdx.x) * 4;
    float4 v = *reinterpret_cast<const float4*>(x + i);
    __half2* p = reinterpret_cast<__half2*>(A_h_g + i);
    p[0] = __halves2half2(__float2half_rn(v.x), __float2half_rn(v.y));
    p[1] = __halves2half2(__float2half_rn(v.z), __float2half_rn(v.w));
}

// ---------------------------------------------------------------------------
// Prep 2: transpose W [K,N] -> Wt [N,K], scale by 64, split into fp16 hi/lo
// (scale keeps the lo limb in the fp16 normal range; epilogue multiplies 1/64)
// ---------------------------------------------------------------------------
__global__ __launch_bounds__(1024)
void transpose_w_kernel(const float* __restrict__ W) {
    __shared__ float tile[32][33];
    const int n0 = blockIdx.x * 32;
    const int k0 = blockIdx.y * 32;
    const int tx = threadIdx.x, ty = threadIdx.y;
    tile[ty][tx] = W[(size_t)(k0 + ty) * N_ + (n0 + tx)];
    __syncthreads();
    const float v = tile[tx][ty] * 64.0f;     // = 64*W[k0+tx][n0+ty]
    __half hi = __float2half_rn(v);
    __half lo = __float2half_rn(v - __half2float(hi));
    const size_t o = (size_t)(n0 + ty) * K_ + (k0 + tx);
    Wt_hi_g[o] = hi;
    Wt_lo_g[o] = lo;
}

// ---------------------------------------------------------------------------
// HMMA GEMM (2-pass fp16): g = (1/64)*(Ah @ (Bhi + Blo)^T) + bias
// BM=128, BN=256, BK=32, 256 threads (2M x 4N warps, 64x64 warp tiles),
// 4-stage cp.async pipeline, mma.sync.m16n8k16 fp16.
// ---------------------------------------------------------------------------
#define BM 128
#define BN 256
#define BKQ 32
#define KPAD 40                    // padded smem row (elems) -> 80B rows
#define NSTAGE 4
#define NITER (K_ / BKQ)           // 32

#define SA    0
#define SBH   (BM * KPAD * 2)                    // 10240
#define SBL   (SBH + BN * KPAD * 2)              // 30720
#define STAGE_BYTES (SBL + BN * KPAD * 2)        // 51200
#define GEMM_SMEM (NSTAGE * STAGE_BYTES)         // 204800

__global__ __launch_bounds__(256, 1)
void sru_gemm_mma_kernel(const __half* __restrict__ Ah,
                         const __half* __restrict__ Bhi,
                         const __half* __restrict__ Blo,
                         const float* __restrict__ bias) {
    extern __shared__ char smem[];
    const uint32_t sb = smem_u32(smem);
    const int tid = threadIdx.x;
    const int lane = tid & 31;
    const int wid = tid >> 5;
    const int wm = wid & 1;        // 0..1  (M warps)
    const int wn = wid >> 1;       // 0..3  (N warps)
    const int m_blk = blockIdx.y * BM;
    const int n_blk = blockIdx.x * BN;

    float acc[4][8][4];
    #pragma unroll
    for (int i = 0; i < 4; i++)
        #pragma unroll
        for (int j = 0; j < 8; j++)
            #pragma unroll
            for (int r = 0; r < 4; r++)
                acc[i][j][r] = 0.0f;

    // ---- stage loader (10 cp.async of 16B per thread) ----
    auto load_stage = [&](int s, int k0) {
        const uint32_t st = sb + s * STAGE_BYTES;
        #pragma unroll
        for (int i = 0; i < 2; i++) {              // A: 512 chunks
            const int ch = tid + 256 * i;
            const int r = ch >> 2, c = ch & 3;
            cp_async16(st + SA + (uint32_t)(r * KPAD * 2 + c * 16),
                       Ah + (size_t)(m_blk + r) * K_ + k0 + c * 8);
        }
        #pragma unroll
        for (int i = 0; i < 4; i++) {              // B: 1024 chunks per limb
            const int ch = tid + 256 * i;
            const int r = ch >> 2, c = ch & 3;
            const size_t g = (size_t)(n_blk + r) * K_ + k0 + c * 8;
            const uint32_t so = (uint32_t)(r * KPAD * 2 + c * 16);
            cp_async16(st + SBH + so, Bhi + g);
            cp_async16(st + SBL + so, Blo + g);
        }
    };

    // prologue: stages 0,1,2
    load_stage(0, 0);          cp_commit();
    load_stage(1, BKQ);        cp_commit();
    load_stage(2, 2 * BKQ);    cp_commit();

    for (int it = 0; it < NITER; it++) {
        cp_wait<2>();
        __syncthreads();

        const uint32_t st = sb + (it % NSTAGE) * STAGE_BYTES;
        #pragma unroll
        for (int ks = 0; ks < 2; ks++) {
            uint32_t aH[4][4];
            const int arow = wm * 64 + (lane & 15);
            const int acol = ks * 16 + (lane >> 4) * 8;
            #pragma unroll
            for (int mt = 0; mt < 4; mt++)
                ldsm_x4(aH[mt], st + SA + (uint32_t)(((arow + mt * 16) * KPAD + acol) * 2));

            const int brow = wn * 64 + (lane & 15);
            #pragma unroll
            for (int nt2 = 0; nt2 < 4; nt2++) {
                const uint32_t off = (uint32_t)(((brow + nt2 * 16) * KPAD + acol) * 2);
                uint32_t bh[4], bl[4];
                ldsm_x4(bh, st + SBH + off);
                ldsm_x4(bl, st + SBL + off);
                #pragma unroll
                for (int mt = 0; mt < 4; mt++) {
                    float* e = acc[mt][2 * nt2];
                    mma_16816_f16(e, aH[mt], bh[0], bh[2]);
                    mma_16816_f16(e, aH[mt], bl[0], bl[2]);
                    float* o = acc[mt][2 * nt2 + 1];
                    mma_16816_f16(o, aH[mt], bh[1], bh[3]);
                    mma_16816_f16(o, aH[mt], bl[1], bl[3]);
                }
            }
        }
        __syncthreads();
        if (it + 3 < NITER) load_stage((it + 3) % NSTAGE, (it + 3) * BKQ);
        cp_commit();
    }

    // ---- epilogue: unscale (1/64), add bias, store fp32 ----
    const float inv = 1.0f / 64.0f;
    #pragma unroll
    for (int nt = 0; nt < 8; nt++) {
        const int col = n_blk + wn * 64 + nt * 8 + (lane & 3) * 2;
        const float bx = __ldg(&bias[col]);
        const float by = __ldg(&bias[col + 1]);
        #pragma unroll
        for (int mt = 0; mt < 4; mt++) {
            const int row = m_blk + wm * 64 + mt * 16 + (lane >> 2);
            float2 v0 = make_float2(fmaf(acc[mt][nt][0], inv, bx),
                                    fmaf(acc[mt][nt][1], inv, by));
            float2 v1 = make_float2(fmaf(acc[mt][nt][2], inv, bx),
                                    fmaf(acc[mt][nt][3], inv, by));
            *reinterpret_cast<float2*>(&g_scratch[(size_t)row * N_ + col]) = v0;
            *reinterpret_cast<float2*>(&g_scratch[(size_t)(row + 8) * N_ + col]) = v1;
        }
    }
}

// ---------------------------------------------------------------------------
// SRU scan: warp-private cp.async-staged pipeline, 16-deep smem ring.
// Warp owns 32 consecutive u-lanes. Per t: 1 cp.async(16B)/lane producer,
// wait_group<14> + __syncwarp consumer. No block barriers.
// ---------------------------------------------------------------------------
#define SCAN_STAGES 16
#define SCAN_SMEM (8 * SCAN_STAGES * 128 * 4)    // 65536 B

__global__ __launch_bounds__(256)
void sru_scan_kernel(const float* __restrict__ c0,
                     const float* __restrict__ Vr,
                     const float* __restrict__ Vf,
                     float* __restrict__ out) {
    extern __shared__ float ssc[];               // [8 warps][16 stages][128 f]
    const int tid = threadIdx.x;
    const int lane = tid & 31;
    const int w = tid >> 5;
    const int blk = blockIdx.x;                  // 128 blocks
    const int b = blk >> 2;
    const int ubase = (blk & 3) * 256 + w * 32;
    const int u = ubase + lane;

    float c = c0[b * U_ + u];
    const float vr = Vr[u];
    const float vf = Vf[u];

    // producer role: lane l loads stream s=(l>>3), 16B at float offset (l&7)*4
    const int s = lane >> 3;
    const int f0 = (lane & 7) * 4;
    const float* gsrc = g_scratch + (size_t)b * T_ * N_ + (size_t)s * U_ + ubase + f0;

    float* wsm = ssc + w * (SCAN_STAGES * 128);
    const uint32_t wbase = smem_u32(wsm);

    // prologue: stages for t = 0..14
    #pragma unroll
    for (int t = 0; t < SCAN_STAGES - 1; t++) {
        cp_async16(wbase + (uint32_t)(t * 512 + s * 128 + f0 * 4),
                   gsrc + (size_t)t * N_);
        cp_commit();
    }

    float* orow = out + (size_t)b * T_ * U_ + u;

    for (int t = 0; t < T_; t++) {
        cp_wait<SCAN_STAGES - 2>();   // oldest stage (t) complete
        __syncwarp();
        const float* stg = wsm + (t & (SCAN_STAGES - 1)) * 128;
        const float a1 = stg[0 * 32 + lane];
        const float a2 = stg[1 * 32 + lane];
        const float a3 = stg[2 * 32 + lane];
        const float a4 = stg[3 * 32 + lane];

        const float fg = 1.0f / (1.0f + __expf(-(a1 + vf * c)));
        const float cn = fg * c + (1.0f - fg) * a2;
        const float r  = 1.0f / (1.0f + __expf(-(a3 + vr * c)));
        const float h  = r * cn + (1.0f - r) * a4;
        c = cn;
        orow[(size_t)t * U_] = h;

        const int tn = t + SCAN_STAGES - 1;
        if (tn < T_) {
            __syncwarp();   // all lanes done reading stage (tn & 15) from t-1 epoch
            cp_async16(wbase + (uint32_t)((tn & (SCAN_STAGES - 1)) * 512 + s * 128 + f0 * 4),
                       gsrc + (size_t)tn * N_);
            cp_commit();
        }
    }
}

// ---------------------------------------------------------------------------
// Host launch.  Inputs: x, h0, c0, W, b, Vr, Vf
// ---------------------------------------------------------------------------
extern "C" void kernel_launch(void* const* d_in, const int* in_sizes, int n_in,
                              void* d_out, int out_size) {
    const float* x  = (const float*)d_in[0];
    // d_in[1] = h0 (unused by reference)
    const float* c0 = (const float*)d_in[2];
    const float* W  = (const float*)d_in[3];
    const float* b  = (const float*)d_in[4];
    const float* Vr = (const float*)d_in[5];
    const float* Vf = (const float*)d_in[6];
    float* out = (float*)d_out;

    void *pAh, *pBhi, *pBlo;
    cudaGetSymbolAddress(&pAh, A_h_g);
    cudaGetSymbolAddress(&pBhi, Wt_hi_g);
    cudaGetSymbolAddress(&pBlo, Wt_lo_g);

    cudaFuncSetAttribute(sru_gemm_mma_kernel,
                         cudaFuncAttributeMaxDynamicSharedMemorySize, GEMM_SMEM);
    cudaFuncSetAttribute(sru_scan_kernel,
                         cudaFuncAttributeMaxDynamicSharedMemorySize, SCAN_SMEM);

    // Prep: round x to fp16, transpose+scale+split W
    split_x_kernel<<<(int)((size_t)M_ * K_ / 4 / 256), 256>>>(x);
    transpose_w_kernel<<<dim3(N_ / 32, K_ / 32), dim3(32, 32)>>>(W);

    // 2-pass fp16 HMMA GEMM
    dim3 gg(N_ / BN, M_ / BM);  // (16, 256)
    sru_gemm_mma_kernel<<<gg, 256, GEMM_SMEM>>>(
        (const __half*)pAh, (const __half*)pBhi, (const __half*)pBlo, b);

    // Scan (warp-staged pipeline)
    sru_scan_kernel<<<128, 256, SCAN_SMEM>>>(c0, Vr, Vf, out);
}

// round 5
// speedup vs baseline: 4.9559x; 1.5426x over previous
#include <cuda_runtime.h>
#include <cuda_fp16.h>
#include <math.h>
#include <stdint.h>

// ---------------------------------------------------------------------------
// Problem constants
// ---------------------------------------------------------------------------
#define B_  32
#define T_  1024
#define D_  1024
#define U_  1024
#define M_  (B_ * T_)     // 32768
#define N_  (4 * U_)      // 4096
#define K_  D_            // 1024

// Device scratch (allocation-free rule: __device__ globals)
__device__ __align__(16) __half g_half[(size_t)M_ * N_];          // 256 MB
__device__ __align__(16) __half A_h_g[(size_t)M_ * K_];           // 64 MB
__device__ __align__(16) __half Wt_h_g[(size_t)N_ * K_];          // 8 MB

// ---------------------------------------------------------------------------
// PTX helpers (base-target instructions only, no sm_103a feature gating)
// ---------------------------------------------------------------------------
__device__ __forceinline__ uint32_t smem_u32(const void* p) {
    uint32_t a;
    asm("{ .reg .u64 t; cvta.to.shared.u64 t, %1; cvt.u32.u64 %0, t; }" : "=r"(a) : "l"(p));
    return a;
}
__device__ __forceinline__ void cp_async16(uint32_t dst, const void* src) {
    asm volatile("cp.async.cg.shared.global [%0], [%1], 16;" :: "r"(dst), "l"(src));
}
__device__ __forceinline__ void cp_commit() {
    asm volatile("cp.async.commit_group;");
}
template <int N>
__device__ __forceinline__ void cp_wait() {
    asm volatile("cp.async.wait_group %0;" :: "n"(N));
}
__device__ __forceinline__ void ldsm_x4(uint32_t* r, uint32_t addr) {
    asm volatile("ldmatrix.sync.aligned.m8n8.x4.shared.b16 {%0,%1,%2,%3}, [%4];"
                 : "=r"(r[0]), "=r"(r[1]), "=r"(r[2]), "=r"(r[3]) : "r"(addr));
}
__device__ __forceinline__ void mma_16816_f16(float* d, const uint32_t* a,
                                              uint32_t b0, uint32_t b1) {
    asm volatile("mma.sync.aligned.m16n8k16.row.col.f32.f16.f16.f32 "
                 "{%0,%1,%2,%3}, {%4,%5,%6,%7}, {%8,%9}, {%0,%1,%2,%3};"
                 : "+f"(d[0]), "+f"(d[1]), "+f"(d[2]), "+f"(d[3])
                 : "r"(a[0]), "r"(a[1]), "r"(a[2]), "r"(a[3]), "r"(b0), "r"(b1));
}

// ---------------------------------------------------------------------------
// Prep 1: round x (fp32 [M,K]) to fp16
// ---------------------------------------------------------------------------
__global__ __launch_bounds__(256)
void split_x_kernel(const float* __restrict__ x) {
    size_t i = ((size_t)blockIdx.x * blockDim.x + threadIdx.x) * 4;
    float4 v = *reinterpret_cast<const float4*>(x + i);
    __half2* p = reinterpret_cast<__half2*>(A_h_g + i);
    p[0] = __halves2half2(__float2half_rn(v.x), __float2half_rn(v.y));
    p[1] = __halves2half2(__float2half_rn(v.z), __float2half_rn(v.w));
}

// ---------------------------------------------------------------------------
// Prep 2: transpose W [K,N] -> Wt [N,K] fp16
// ---------------------------------------------------------------------------
__global__ __launch_bounds__(1024)
void transpose_w_kernel(const float* __restrict__ W) {
    __shared__ float tile[32][33];
    const int n0 = blockIdx.x * 32;
    const int k0 = blockIdx.y * 32;
    const int tx = threadIdx.x, ty = threadIdx.y;
    tile[ty][tx] = W[(size_t)(k0 + ty) * N_ + (n0 + tx)];
    __syncthreads();
    Wt_h_g[(size_t)(n0 + ty) * K_ + (k0 + tx)] = __float2half_rn(tile[tx][ty]);
}

// ---------------------------------------------------------------------------
// HMMA GEMM (single-pass fp16): g = half(Ah @ Bh^T + bias)
// BM=128, BN=256, BK=32, 256 threads (2M x 4N warps, 64x64 warp tiles),
// 5-stage cp.async pipeline, mma.sync.m16n8k16 fp16, fp32 accum.
// ---------------------------------------------------------------------------
#define BM 128
#define BN 256
#define BKQ 32
#define KPAD 40                    // padded smem row (elems) -> 80B rows
#define NSTAGE 5
#define NITER (K_ / BKQ)           // 32

#define SA    0
#define SBH   (BM * KPAD * 2)                    // 10240
#define STAGE_BYTES (SBH + BN * KPAD * 2)        // 30720
#define GEMM_SMEM (NSTAGE * STAGE_BYTES)         // 153600

__global__ __launch_bounds__(256, 1)
void sru_gemm_mma_kernel(const __half* __restrict__ Ah,
                         const __half* __restrict__ Bh,
                         const float* __restrict__ bias) {
    extern __shared__ char smem[];
    const uint32_t sb = smem_u32(smem);
    const int tid = threadIdx.x;
    const int lane = tid & 31;
    const int wid = tid >> 5;
    const int wm = wid & 1;        // 0..1  (M warps)
    const int wn = wid >> 1;       // 0..3  (N warps)
    const int m_blk = blockIdx.y * BM;
    const int n_blk = blockIdx.x * BN;

    float acc[4][8][4];
    #pragma unroll
    for (int i = 0; i < 4; i++)
        #pragma unroll
        for (int j = 0; j < 8; j++)
            #pragma unroll
            for (int r = 0; r < 4; r++)
                acc[i][j][r] = 0.0f;

    // ---- stage loader (6 cp.async of 16B per thread) ----
    auto load_stage = [&](int s, int k0) {
        const uint32_t st = sb + s * STAGE_BYTES;
        #pragma unroll
        for (int i = 0; i < 2; i++) {              // A: 512 chunks
            const int ch = tid + 256 * i;
            const int r = ch >> 2, c = ch & 3;
            cp_async16(st + SA + (uint32_t)(r * KPAD * 2 + c * 16),
                       Ah + (size_t)(m_blk + r) * K_ + k0 + c * 8);
        }
        #pragma unroll
        for (int i = 0; i < 4; i++) {              // B: 1024 chunks
            const int ch = tid + 256 * i;
            const int r = ch >> 2, c = ch & 3;
            cp_async16(st + SBH + (uint32_t)(r * KPAD * 2 + c * 16),
                       Bh + (size_t)(n_blk + r) * K_ + k0 + c * 8);
        }
    };

    // prologue: stages 0..3
    load_stage(0, 0);          cp_commit();
    load_stage(1, BKQ);        cp_commit();
    load_stage(2, 2 * BKQ);    cp_commit();
    load_stage(3, 3 * BKQ);    cp_commit();

    for (int it = 0; it < NITER; it++) {
        cp_wait<3>();
        __syncthreads();

        const uint32_t st = sb + (it % NSTAGE) * STAGE_BYTES;
        #pragma unroll
        for (int ks = 0; ks < 2; ks++) {
            uint32_t aH[4][4];
            const int arow = wm * 64 + (lane & 15);
            const int acol = ks * 16 + (lane >> 4) * 8;
            #pragma unroll
            for (int mt = 0; mt < 4; mt++)
                ldsm_x4(aH[mt], st + SA + (uint32_t)(((arow + mt * 16) * KPAD + acol) * 2));

            const int brow = wn * 64 + (lane & 15);
            #pragma unroll
            for (int nt2 = 0; nt2 < 4; nt2++) {
                uint32_t bh[4];
                ldsm_x4(bh, st + SBH + (uint32_t)(((brow + nt2 * 16) * KPAD + acol) * 2));
                #pragma unroll
                for (int mt = 0; mt < 4; mt++) {
                    mma_16816_f16(acc[mt][2 * nt2],     aH[mt], bh[0], bh[2]);
                    mma_16816_f16(acc[mt][2 * nt2 + 1], aH[mt], bh[1], bh[3]);
                }
            }
        }
        __syncthreads();
        if (it + 4 < NITER) load_stage((it + 4) % NSTAGE, (it + 4) * BKQ);
        cp_commit();
    }

    // ---- epilogue: add bias, store fp16 g ----
    #pragma unroll
    for (int nt = 0; nt < 8; nt++) {
        const int col = n_blk + wn * 64 + nt * 8 + (lane & 3) * 2;
        const float bx = __ldg(&bias[col]);
        const float by = __ldg(&bias[col + 1]);
        #pragma unroll
        for (int mt = 0; mt < 4; mt++) {
            const int row = m_blk + wm * 64 + mt * 16 + (lane >> 2);
            __half2 v0 = __floats2half2_rn(acc[mt][nt][0] + bx, acc[mt][nt][1] + by);
            __half2 v1 = __floats2half2_rn(acc[mt][nt][2] + bx, acc[mt][nt][3] + by);
            *reinterpret_cast<__half2*>(&g_half[(size_t)row * N_ + col]) = v0;
            *reinterpret_cast<__half2*>(&g_half[(size_t)(row + 8) * N_ + col]) = v1;
        }
    }
}

// ---------------------------------------------------------------------------
// SRU scan: warp-private cp.async-staged pipeline over fp16 g.
// 32-deep ring, 256 B/stage/warp. Lanes 0-15 produce (16B each covering
// 4 streams x 32 halves); all lanes consume. No block barriers.
// ---------------------------------------------------------------------------
#define SCAN_STAGES 32
#define SCAN_SMEM (8 * SCAN_STAGES * 128 * 2)    // 65536 B

__global__ __launch_bounds__(256)
void sru_scan_kernel(const float* __restrict__ c0,
                     const float* __restrict__ Vr,
                     const float* __restrict__ Vf,
                     float* __restrict__ out) {
    extern __shared__ __half ssc[];              // [8 warps][32 stages][128 h]
    const int tid = threadIdx.x;
    const int lane = tid & 31;
    const int w = tid >> 5;
    const int blk = blockIdx.x;                  // 128 blocks
    const int b = blk >> 2;
    const int ubase = (blk & 3) * 256 + w * 32;
    const int u = ubase + lane;

    float c = c0[b * U_ + u];
    const float vr = Vr[u];
    const float vf = Vf[u];

    // producer role (lanes 0-15): stream s = lane>>2, 8 halves at (lane&3)*8
    const int s = lane >> 2;
    const int f0 = (lane & 3) * 8;
    const __half* gsrc = g_half + (size_t)b * T_ * N_ + (size_t)s * U_ + ubase + f0;

    __half* wsm = ssc + w * (SCAN_STAGES * 128);
    const uint32_t wbase = smem_u32(wsm);

    // prologue: stages for t = 0..30
    #pragma unroll
    for (int t = 0; t < SCAN_STAGES - 1; t++) {
        if (lane < 16)
            cp_async16(wbase + (uint32_t)(t * 256 + s * 64 + f0 * 2),
                       gsrc + (size_t)t * N_);
        cp_commit();
    }

    float* orow = out + (size_t)b * T_ * U_ + u;

    for (int t = 0; t < T_; t++) {
        cp_wait<SCAN_STAGES - 2>();   // oldest stage (t) complete
        __syncwarp();
        const __half* stg = wsm + (t & (SCAN_STAGES - 1)) * 128;
        const float a1 = __half2float(stg[0 * 32 + lane]);
        const float a2 = __half2float(stg[1 * 32 + lane]);
        const float a3 = __half2float(stg[2 * 32 + lane]);
        const float a4 = __half2float(stg[3 * 32 + lane]);

        const float fg = 1.0f / (1.0f + __expf(-(a1 + vf * c)));
        const float cn = fg * c + (1.0f - fg) * a2;
        const float r  = 1.0f / (1.0f + __expf(-(a3 + vr * c)));
        const float h  = r * cn + (1.0f - r) * a4;
        c = cn;
        orow[(size_t)t * U_] = h;

        const int tn = t + SCAN_STAGES - 1;
        if (tn < T_) {
            __syncwarp();   // all lanes done reading the stage being overwritten
            if (lane < 16)
                cp_async16(wbase + (uint32_t)((tn & (SCAN_STAGES - 1)) * 256 + s * 64 + f0 * 2),
                           gsrc + (size_t)tn * N_);
            cp_commit();
        }
    }
}

// ---------------------------------------------------------------------------
// Host launch.  Inputs: x, h0, c0, W, b, Vr, Vf
// ---------------------------------------------------------------------------
extern "C" void kernel_launch(void* const* d_in, const int* in_sizes, int n_in,
                              void* d_out, int out_size) {
    const float* x  = (const float*)d_in[0];
    // d_in[1] = h0 (unused by reference)
    const float* c0 = (const float*)d_in[2];
    const float* W  = (const float*)d_in[3];
    const float* b  = (const float*)d_in[4];
    const float* Vr = (const float*)d_in[5];
    const float* Vf = (const float*)d_in[6];
    float* out = (float*)d_out;

    void *pAh, *pBh;
    cudaGetSymbolAddress(&pAh, A_h_g);
    cudaGetSymbolAddress(&pBh, Wt_h_g);

    cudaFuncSetAttribute(sru_gemm_mma_kernel,
                         cudaFuncAttributeMaxDynamicSharedMemorySize, GEMM_SMEM);
    cudaFuncSetAttribute(sru_scan_kernel,
                         cudaFuncAttributeMaxDynamicSharedMemorySize, SCAN_SMEM);

    // Prep: round x to fp16, transpose+round W
    split_x_kernel<<<(int)((size_t)M_ * K_ / 4 / 256), 256>>>(x);
    transpose_w_kernel<<<dim3(N_ / 32, K_ / 32), dim3(32, 32)>>>(W);

    // Single-pass fp16 HMMA GEMM
    dim3 gg(N_ / BN, M_ / BM);  // (16, 256)
    sru_gemm_mma_kernel<<<gg, 256, GEMM_SMEM>>>(
        (const __half*)pAh, (const __half*)pBh, b);

    // Scan (warp-staged pipeline over fp16 g)
    sru_scan_kernel<<<128, 256, SCAN_SMEM>>>(c0, Vr, Vf, out);
}

// round 6
// speedup vs baseline: 5.4001x; 1.0896x over previous
#include <cuda_runtime.h>
#include <cuda_fp16.h>
#include <math.h>
#include <stdint.h>

// ---------------------------------------------------------------------------
// Problem constants
// ---------------------------------------------------------------------------
#define B_  32
#define T_  1024
#define D_  1024
#define U_  1024
#define M_  (B_ * T_)     // 32768
#define N_  (4 * U_)      // 4096
#define K_  D_            // 1024

// Device scratch (allocation-free rule: __device__ globals)
__device__ __align__(16) __half g_half[(size_t)M_ * N_];          // 256 MB
__device__ __align__(16) __half A_h_g[(size_t)M_ * K_];           // 64 MB
__device__ __align__(16) __half Wt_h_g[(size_t)N_ * K_];          // 8 MB

// ---------------------------------------------------------------------------
// PTX helpers (base-target instructions only, no sm_103a feature gating)
// ---------------------------------------------------------------------------
__device__ __forceinline__ uint32_t smem_u32(const void* p) {
    uint32_t a;
    asm("{ .reg .u64 t; cvta.to.shared.u64 t, %1; cvt.u32.u64 %0, t; }" : "=r"(a) : "l"(p));
    return a;
}
__device__ __forceinline__ void cp_async16(uint32_t dst, const void* src) {
    asm volatile("cp.async.cg.shared.global [%0], [%1], 16;" :: "r"(dst), "l"(src));
}
__device__ __forceinline__ void cp_commit() {
    asm volatile("cp.async.commit_group;");
}
template <int N>
__device__ __forceinline__ void cp_wait() {
    asm volatile("cp.async.wait_group %0;" :: "n"(N));
}
__device__ __forceinline__ void ldsm_x4(uint32_t* r, uint32_t addr) {
    asm volatile("ldmatrix.sync.aligned.m8n8.x4.shared.b16 {%0,%1,%2,%3}, [%4];"
                 : "=r"(r[0]), "=r"(r[1]), "=r"(r[2]), "=r"(r[3]) : "r"(addr));
}
__device__ __forceinline__ void mma_16816_f16(float* d, const uint32_t* a,
                                              uint32_t b0, uint32_t b1) {
    asm volatile("mma.sync.aligned.m16n8k16.row.col.f32.f16.f16.f32 "
                 "{%0,%1,%2,%3}, {%4,%5,%6,%7}, {%8,%9}, {%0,%1,%2,%3};"
                 : "+f"(d[0]), "+f"(d[1]), "+f"(d[2]), "+f"(d[3])
                 : "r"(a[0]), "r"(a[1]), "r"(a[2]), "r"(a[3]), "r"(b0), "r"(b1));
}

// ---------------------------------------------------------------------------
// Prep 1: round x (fp32 [M,K]) to fp16
// ---------------------------------------------------------------------------
__global__ __launch_bounds__(256)
void split_x_kernel(const float* __restrict__ x) {
    size_t i = ((size_t)blockIdx.x * blockDim.x + threadIdx.x) * 4;
    float4 v = *reinterpret_cast<const float4*>(x + i);
    __half2* p = reinterpret_cast<__half2*>(A_h_g + i);
    p[0] = __halves2half2(__float2half_rn(v.x), __float2half_rn(v.y));
    p[1] = __halves2half2(__float2half_rn(v.z), __float2half_rn(v.w));
}

// ---------------------------------------------------------------------------
// Prep 2: transpose W [K,N] -> Wt [N,K] fp16
// ---------------------------------------------------------------------------
__global__ __launch_bounds__(1024)
void transpose_w_kernel(const float* __restrict__ W) {
    __shared__ float tile[32][33];
    const int n0 = blockIdx.x * 32;
    const int k0 = blockIdx.y * 32;
    const int tx = threadIdx.x, ty = threadIdx.y;
    tile[ty][tx] = W[(size_t)(k0 + ty) * N_ + (n0 + tx)];
    __syncthreads();
    Wt_h_g[(size_t)(n0 + ty) * K_ + (k0 + tx)] = __float2half_rn(tile[tx][ty]);
}

// ---------------------------------------------------------------------------
// HMMA GEMM (single-pass fp16): g = half(Ah @ Bh^T + bias)
// BM=128, BN=256, BK=32, 256 threads (2M x 4N warps, 64x64 warp tiles),
// 5-stage cp.async pipeline, one barrier per iteration.
// ---------------------------------------------------------------------------
#define BM 128
#define BN 256
#define BKQ 32
#define KPAD 40                    // padded smem row (elems) -> 80B rows
#define NSTAGE 5
#define NITER (K_ / BKQ)           // 32

#define SA    0
#define SBH   (BM * KPAD * 2)                    // 10240
#define STAGE_BYTES (SBH + BN * KPAD * 2)        // 30720
#define GEMM_SMEM (NSTAGE * STAGE_BYTES)         // 153600

__global__ __launch_bounds__(256, 1)
void sru_gemm_mma_kernel(const __half* __restrict__ Ah,
                         const __half* __restrict__ Bh,
                         const float* __restrict__ bias) {
    extern __shared__ char smem[];
    const uint32_t sb = smem_u32(smem);
    const int tid = threadIdx.x;
    const int lane = tid & 31;
    const int wid = tid >> 5;
    const int wm = wid & 1;        // 0..1  (M warps)
    const int wn = wid >> 1;       // 0..3  (N warps)
    const int m_blk = blockIdx.y * BM;
    const int n_blk = blockIdx.x * BN;

    float acc[4][8][4];
    #pragma unroll
    for (int i = 0; i < 4; i++)
        #pragma unroll
        for (int j = 0; j < 8; j++)
            #pragma unroll
            for (int r = 0; r < 4; r++)
                acc[i][j][r] = 0.0f;

    // ---- stage loader (6 cp.async of 16B per thread) ----
    auto load_stage = [&](int s, int k0) {
        const uint32_t st = sb + s * STAGE_BYTES;
        #pragma unroll
        for (int i = 0; i < 2; i++) {              // A: 512 chunks
            const int ch = tid + 256 * i;
            const int r = ch >> 2, c = ch & 3;
            cp_async16(st + SA + (uint32_t)(r * KPAD * 2 + c * 16),
                       Ah + (size_t)(m_blk + r) * K_ + k0 + c * 8);
        }
        #pragma unroll
        for (int i = 0; i < 4; i++) {              // B: 1024 chunks
            const int ch = tid + 256 * i;
            const int r = ch >> 2, c = ch & 3;
            cp_async16(st + SBH + (uint32_t)(r * KPAD * 2 + c * 16),
                       Bh + (size_t)(n_blk + r) * K_ + k0 + c * 8);
        }
    };

    // prologue: stages 0..3
    load_stage(0, 0);          cp_commit();
    load_stage(1, BKQ);        cp_commit();
    load_stage(2, 2 * BKQ);    cp_commit();
    load_stage(3, 3 * BKQ);    cp_commit();

    for (int it = 0; it < NITER; it++) {
        cp_wait<3>();
        __syncthreads();   // readers of stage (it-1)%5 done + my stage (it)%5 visible

        const uint32_t st = sb + (it % NSTAGE) * STAGE_BYTES;
        #pragma unroll
        for (int ks = 0; ks < 2; ks++) {
            uint32_t aH[4][4];
            const int arow = wm * 64 + (lane & 15);
            const int acol = ks * 16 + (lane >> 4) * 8;
            #pragma unroll
            for (int mt = 0; mt < 4; mt++)
                ldsm_x4(aH[mt], st + SA + (uint32_t)(((arow + mt * 16) * KPAD + acol) * 2));

            const int brow = wn * 64 + (lane & 15);
            #pragma unroll
            for (int nt2 = 0; nt2 < 4; nt2++) {
                uint32_t bh[4];
                ldsm_x4(bh, st + SBH + (uint32_t)(((brow + nt2 * 16) * KPAD + acol) * 2));
                #pragma unroll
                for (int mt = 0; mt < 4; mt++) {
                    mma_16816_f16(acc[mt][2 * nt2],     aH[mt], bh[0], bh[2]);
                    mma_16816_f16(acc[mt][2 * nt2 + 1], aH[mt], bh[1], bh[3]);
                }
            }
        }
        // no second barrier: next iteration's top barrier (after cp_wait)
        // orders these smem reads before the overwrite of stage (it+4)%5.
        if (it + 4 < NITER) load_stage((it + 4) % NSTAGE, (it + 4) * BKQ);
        cp_commit();
    }

    // ---- epilogue: add bias, store fp16 g ----
    #pragma unroll
    for (int nt = 0; nt < 8; nt++) {
        const int col = n_blk + wn * 64 + nt * 8 + (lane & 3) * 2;
        const float bx = __ldg(&bias[col]);
        const float by = __ldg(&bias[col + 1]);
        #pragma unroll
        for (int mt = 0; mt < 4; mt++) {
            const int row = m_blk + wm * 64 + mt * 16 + (lane >> 2);
            __half2 v0 = __floats2half2_rn(acc[mt][nt][0] + bx, acc[mt][nt][1] + by);
            __half2 v1 = __floats2half2_rn(acc[mt][nt][2] + bx, acc[mt][nt][3] + by);
            *reinterpret_cast<__half2*>(&g_half[(size_t)row * N_ + col]) = v0;
            *reinterpret_cast<__half2*>(&g_half[(size_t)(row + 8) * N_ + col]) = v1;
        }
    }
}

// ---------------------------------------------------------------------------
// SRU scan: direct-LDG register double buffer, 16 timesteps per block.
// No smem, no barriers. MLP ~64 halves in flight per thread.
// ---------------------------------------------------------------------------
#define TB 16   // timesteps per register buffer

struct ScanBuf { __half v[TB][4]; };

__device__ __forceinline__ void scan_load(ScanBuf& bf, const __half* __restrict__ gp, int t0) {
    #pragma unroll
    for (int j = 0; j < TB; j++) {
        const __half* row = gp + (size_t)(t0 + j) * N_;
        bf.v[j][0] = __ldcs(row);
        bf.v[j][1] = __ldcs(row + U_);
        bf.v[j][2] = __ldcs(row + 2 * U_);
        bf.v[j][3] = __ldcs(row + 3 * U_);
    }
}

__device__ __forceinline__ void scan_compute(const ScanBuf& bf, float& c,
                                             float vr, float vf,
                                             float* __restrict__ orow, int t0) {
    #pragma unroll
    for (int j = 0; j < TB; j++) {
        const float a1 = __half2float(bf.v[j][0]);
        const float a2 = __half2float(bf.v[j][1]);
        const float a3 = __half2float(bf.v[j][2]);
        const float a4 = __half2float(bf.v[j][3]);
        const float fg = __fdividef(1.0f, 1.0f + __expf(-(a1 + vf * c)));
        const float r  = __fdividef(1.0f, 1.0f + __expf(-(a3 + vr * c)));
        const float cn = fg * c + (1.0f - fg) * a2;
        const float h  = r * cn + (1.0f - r) * a4;
        c = cn;
        __stcs(orow + (size_t)(t0 + j) * U_, h);
    }
}

__global__ __launch_bounds__(256)
void sru_scan_kernel(const float* __restrict__ c0,
                     const float* __restrict__ Vr,
                     const float* __restrict__ Vf,
                     float* __restrict__ out) {
    const int idx = blockIdx.x * blockDim.x + threadIdx.x;  // 0 .. B*U-1
    const int b = idx >> 10;           // / U_
    const int u = idx & (U_ - 1);

    float c = c0[idx];
    const float vr = Vr[u];
    const float vf = Vf[u];

    const __half* gp = g_half + (size_t)b * T_ * N_ + u;
    float* orow = out + (size_t)b * T_ * U_ + u;

    ScanBuf bufA, bufB;
    scan_load(bufA, gp, 0);

    #pragma unroll 1
    for (int t0 = 0; t0 < T_; t0 += 2 * TB) {
        scan_load(bufB, gp, t0 + TB);
        scan_compute(bufA, c, vr, vf, orow, t0);
        if (t0 + 2 * TB < T_) scan_load(bufA, gp, t0 + 2 * TB);
        scan_compute(bufB, c, vr, vf, orow, t0 + TB);
    }
}

// ---------------------------------------------------------------------------
// Host launch.  Inputs: x, h0, c0, W, b, Vr, Vf
// ---------------------------------------------------------------------------
extern "C" void kernel_launch(void* const* d_in, const int* in_sizes, int n_in,
                              void* d_out, int out_size) {
    const float* x  = (const float*)d_in[0];
    // d_in[1] = h0 (unused by reference)
    const float* c0 = (const float*)d_in[2];
    const float* W  = (const float*)d_in[3];
    const float* b  = (const float*)d_in[4];
    const float* Vr = (const float*)d_in[5];
    const float* Vf = (const float*)d_in[6];
    float* out = (float*)d_out;

    void *pAh, *pBh;
    cudaGetSymbolAddress(&pAh, A_h_g);
    cudaGetSymbolAddress(&pBh, Wt_h_g);

    cudaFuncSetAttribute(sru_gemm_mma_kernel,
                         cudaFuncAttributeMaxDynamicSharedMemorySize, GEMM_SMEM);

    // Prep: round x to fp16, transpose+round W
    split_x_kernel<<<(int)((size_t)M_ * K_ / 4 / 256), 256>>>(x);
    transpose_w_kernel<<<dim3(N_ / 32, K_ / 32), dim3(32, 32)>>>(W);

    // Single-pass fp16 HMMA GEMM
    dim3 gg(N_ / BN, M_ / BM);  // (16, 256)
    sru_gemm_mma_kernel<<<gg, 256, GEMM_SMEM>>>(
        (const __half*)pAh, (const __half*)pBh, b);

    // Scan (register double-buffered direct loads)
    sru_scan_kernel<<<(B_ * U_) / 256, 256>>>(c0, Vr, Vf, out);
}

// round 7
// speedup vs baseline: 5.9454x; 1.1010x over previous
#include <cuda_runtime.h>
#include <cuda_fp16.h>
#include <math.h>
#include <stdint.h>

// ---------------------------------------------------------------------------
// Problem constants
// ---------------------------------------------------------------------------
#define B_  32
#define T_  1024
#define D_  1024
#define U_  1024
#define M_  (B_ * T_)     // 32768
#define N_  (4 * U_)      // 4096
#define K_  D_            // 1024

// g layout: [B][tb=128][stream=4][U][ti=8], t = tb*8 + ti
//   OFF(b,tb,s,u,ti) = ((((b*128+tb)*4+s)*1024+u)*8+ti
__device__ __align__(16) __half g_half[(size_t)M_ * N_];          // 256 MB
__device__ __align__(16) __half A_h_g[(size_t)M_ * K_];           // 64 MB
__device__ __align__(16) __half Wt_h_g[(size_t)N_ * K_];          // 8 MB

// ---------------------------------------------------------------------------
// PTX helpers (base-target instructions only, no sm_103a feature gating)
// ---------------------------------------------------------------------------
__device__ __forceinline__ uint32_t smem_u32(const void* p) {
    uint32_t a;
    asm("{ .reg .u64 t; cvta.to.shared.u64 t, %1; cvt.u32.u64 %0, t; }" : "=r"(a) : "l"(p));
    return a;
}
__device__ __forceinline__ void cp_async16(uint32_t dst, const void* src) {
    asm volatile("cp.async.cg.shared.global [%0], [%1], 16;" :: "r"(dst), "l"(src));
}
__device__ __forceinline__ void cp_commit() {
    asm volatile("cp.async.commit_group;");
}
template <int N>
__device__ __forceinline__ void cp_wait() {
    asm volatile("cp.async.wait_group %0;" :: "n"(N));
}
__device__ __forceinline__ void ldsm_x4(uint32_t* r, uint32_t addr) {
    asm volatile("ldmatrix.sync.aligned.m8n8.x4.shared.b16 {%0,%1,%2,%3}, [%4];"
                 : "=r"(r[0]), "=r"(r[1]), "=r"(r[2]), "=r"(r[3]) : "r"(addr));
}
__device__ __forceinline__ void mma_16816_f16(float* d, const uint32_t* a,
                                              uint32_t b0, uint32_t b1) {
    asm volatile("mma.sync.aligned.m16n8k16.row.col.f32.f16.f16.f32 "
                 "{%0,%1,%2,%3}, {%4,%5,%6,%7}, {%8,%9}, {%0,%1,%2,%3};"
                 : "+f"(d[0]), "+f"(d[1]), "+f"(d[2]), "+f"(d[3])
                 : "r"(a[0]), "r"(a[1]), "r"(a[2]), "r"(a[3]), "r"(b0), "r"(b1));
}
__device__ __forceinline__ float2 h2f2(uint32_t u) {
    __half2 h = *reinterpret_cast<__half2*>(&u);
    return __half22float2(h);
}

// ---------------------------------------------------------------------------
// Prep 1: round x (fp32 [M,K]) to fp16
// ---------------------------------------------------------------------------
__global__ __launch_bounds__(256)
void split_x_kernel(const float* __restrict__ x) {
    size_t i = ((size_t)blockIdx.x * blockDim.x + threadIdx.x) * 4;
    float4 v = *reinterpret_cast<const float4*>(x + i);
    __half2* p = reinterpret_cast<__half2*>(A_h_g + i);
    p[0] = __halves2half2(__float2half_rn(v.x), __float2half_rn(v.y));
    p[1] = __halves2half2(__float2half_rn(v.z), __float2half_rn(v.w));
}

// ---------------------------------------------------------------------------
// Prep 2: transpose W [K,N] -> Wt [N,K] fp16
// ---------------------------------------------------------------------------
__global__ __launch_bounds__(1024)
void transpose_w_kernel(const float* __restrict__ W) {
    __shared__ float tile[32][33];
    const int n0 = blockIdx.x * 32;
    const int k0 = blockIdx.y * 32;
    const int tx = threadIdx.x, ty = threadIdx.y;
    tile[ty][tx] = W[(size_t)(k0 + ty) * N_ + (n0 + tx)];
    __syncthreads();
    Wt_h_g[(size_t)(n0 + ty) * K_ + (k0 + tx)] = __float2half_rn(tile[tx][ty]);
}

// ---------------------------------------------------------------------------
// HMMA GEMM (single-pass fp16): g = half(Ah @ Bh^T + bias), scan-layout store
// ---------------------------------------------------------------------------
#define BM 128
#define BN 256
#define BKQ 32
#define KPAD 40                    // padded smem row (elems) -> 80B rows
#define NSTAGE 5
#define NITER (K_ / BKQ)           // 32

#define SA    0
#define SBH   (BM * KPAD * 2)                    // 10240
#define STAGE_BYTES (SBH + BN * KPAD * 2)        // 30720
#define GEMM_SMEM (NSTAGE * STAGE_BYTES)         // 153600

__global__ __launch_bounds__(256, 1)
void sru_gemm_mma_kernel(const __half* __restrict__ Ah,
                         const __half* __restrict__ Bh,
                         const float* __restrict__ bias) {
    extern __shared__ char smem[];
    const uint32_t sb = smem_u32(smem);
    const int tid = threadIdx.x;
    const int lane = tid & 31;
    const int wid = tid >> 5;
    const int wm = wid & 1;        // 0..1  (M warps)
    const int wn = wid >> 1;       // 0..3  (N warps)
    const int m_blk = blockIdx.y * BM;
    const int n_blk = blockIdx.x * BN;

    float acc[4][8][4];
    #pragma unroll
    for (int i = 0; i < 4; i++)
        #pragma unroll
        for (int j = 0; j < 8; j++)
            #pragma unroll
            for (int r = 0; r < 4; r++)
                acc[i][j][r] = 0.0f;

    // ---- stage loader (6 cp.async of 16B per thread) ----
    auto load_stage = [&](int s, int k0) {
        const uint32_t st = sb + s * STAGE_BYTES;
        #pragma unroll
        for (int i = 0; i < 2; i++) {              // A: 512 chunks
            const int ch = tid + 256 * i;
            const int r = ch >> 2, c = ch & 3;
            cp_async16(st + SA + (uint32_t)(r * KPAD * 2 + c * 16),
                       Ah + (size_t)(m_blk + r) * K_ + k0 + c * 8);
        }
        #pragma unroll
        for (int i = 0; i < 4; i++) {              // B: 1024 chunks
            const int ch = tid + 256 * i;
            const int r = ch >> 2, c = ch & 3;
            cp_async16(st + SBH + (uint32_t)(r * KPAD * 2 + c * 16),
                       Bh + (size_t)(n_blk + r) * K_ + k0 + c * 8);
        }
    };

    // prologue: stages 0..3
    load_stage(0, 0);          cp_commit();
    load_stage(1, BKQ);        cp_commit();
    load_stage(2, 2 * BKQ);    cp_commit();
    load_stage(3, 3 * BKQ);    cp_commit();

    for (int it = 0; it < NITER; it++) {
        cp_wait<3>();
        __syncthreads();   // readers of stage (it-1)%5 done + stage (it)%5 visible

        const uint32_t st = sb + (it % NSTAGE) * STAGE_BYTES;
        #pragma unroll
        for (int ks = 0; ks < 2; ks++) {
            uint32_t aH[4][4];
            const int arow = wm * 64 + (lane & 15);
            const int acol = ks * 16 + (lane >> 4) * 8;
            #pragma unroll
            for (int mt = 0; mt < 4; mt++)
                ldsm_x4(aH[mt], st + SA + (uint32_t)(((arow + mt * 16) * KPAD + acol) * 2));

            const int brow = wn * 64 + (lane & 15);
            #pragma unroll
            for (int nt2 = 0; nt2 < 4; nt2++) {
                uint32_t bh[4];
                ldsm_x4(bh, st + SBH + (uint32_t)(((brow + nt2 * 16) * KPAD + acol) * 2));
                #pragma unroll
                for (int mt = 0; mt < 4; mt++) {
                    mma_16816_f16(acc[mt][2 * nt2],     aH[mt], bh[0], bh[2]);
                    mma_16816_f16(acc[mt][2 * nt2 + 1], aH[mt], bh[1], bh[3]);
                }
            }
        }
        // next iteration's top barrier orders these reads before the overwrite
        if (it + 4 < NITER) load_stage((it + 4) % NSTAGE, (it + 4) * BKQ);
        cp_commit();
    }

    // ---- epilogue: bias + fp16 store into scan layout ----
    // row r -> b=r>>10, t=r&1023, tb=t>>3, ti=t&7 (ti == lane>>2 here);
    // col n -> s=n>>10, u=n&1023. Per warp each (mt,nt,pair) covers a full
    // contiguous 128B region (8 u x 8 ti of 2B halves).
    const int bI = m_blk >> 10;
    const int sI = n_blk >> 10;
    const int ti = lane >> 2;
    const int tBase = (m_blk & 1023) + wm * 64;
    const int uBase = (n_blk & 1023) + wn * 64;
    #pragma unroll
    for (int nt = 0; nt < 8; nt++) {
        const int col = n_blk + wn * 64 + nt * 8 + (lane & 3) * 2;
        const float bx = __ldg(&bias[col]);
        const float by = __ldg(&bias[col + 1]);
        const int u0 = uBase + nt * 8 + (lane & 3) * 2;
        #pragma unroll
        for (int mt = 0; mt < 4; mt++) {
            const int tl = tBase + mt * 16 + ti;
            const size_t base = (((size_t)bI * 128 + (tl >> 3)) * 4 + sI) * 1024;
            g_half[(base + u0)     * 8 + ti] = __float2half_rn(acc[mt][nt][0] + bx);
            g_half[(base + u0 + 1) * 8 + ti] = __float2half_rn(acc[mt][nt][1] + by);
            g_half[(base + 4096 + u0)     * 8 + ti] = __float2half_rn(acc[mt][nt][2] + bx);
            g_half[(base + 4096 + u0 + 1) * 8 + ti] = __float2half_rn(acc[mt][nt][3] + by);
        }
    }
}

// ---------------------------------------------------------------------------
// SRU scan over the [B][tb][s][U][8] layout: 8 LDG.128 per 16 timesteps,
// register double buffer, no barriers.
// ---------------------------------------------------------------------------
struct ScanBuf { uint4 q[2][4]; };   // [tb-half][stream], 8 halves (ti) each

__device__ __forceinline__ void scan_load(ScanBuf& bf, const uint4* __restrict__ gq,
                                          int tb0) {
    #pragma unroll
    for (int i = 0; i < 2; i++)
        #pragma unroll
        for (int s = 0; s < 4; s++)
            bf.q[i][s] = __ldcs(gq + ((size_t)(tb0 + i) * 4 + s) * 1024);
}

__device__ __forceinline__ void unpack8(float* a, uint4 q) {
    float2 t;
    t = h2f2(q.x); a[0] = t.x; a[1] = t.y;
    t = h2f2(q.y); a[2] = t.x; a[3] = t.y;
    t = h2f2(q.z); a[4] = t.x; a[5] = t.y;
    t = h2f2(q.w); a[6] = t.x; a[7] = t.y;
}

__device__ __forceinline__ void scan_compute(const ScanBuf& bf, float& c,
                                             float vr, float vf,
                                             float* __restrict__ orow, int t0) {
    #pragma unroll
    for (int i = 0; i < 2; i++) {
        float a1[8], a2[8], a3[8], a4[8];
        unpack8(a1, bf.q[i][0]);
        unpack8(a2, bf.q[i][1]);
        unpack8(a3, bf.q[i][2]);
        unpack8(a4, bf.q[i][3]);
        #pragma unroll
        for (int ti = 0; ti < 8; ti++) {
            const float fg = __fdividef(1.0f, 1.0f + __expf(-(a1[ti] + vf * c)));
            const float r  = __fdividef(1.0f, 1.0f + __expf(-(a3[ti] + vr * c)));
            const float cn = fg * c + (1.0f - fg) * a2[ti];
            const float h  = r * cn + (1.0f - r) * a4[ti];
            c = cn;
            __stcs(orow + (size_t)(t0 + i * 8 + ti) * U_, h);
        }
    }
}

__global__ __launch_bounds__(256)
void sru_scan_kernel(const float* __restrict__ c0,
                     const float* __restrict__ Vr,
                     const float* __restrict__ Vf,
                     float* __restrict__ out) {
    const int idx = blockIdx.x * blockDim.x + threadIdx.x;  // 0 .. B*U-1
    const int b = idx >> 10;
    const int u = idx & (U_ - 1);

    float c = c0[idx];
    const float vr = Vr[u];
    const float vf = Vf[u];

    const uint4* gq = reinterpret_cast<const uint4*>(g_half)
                      + (size_t)b * 128 * 4 * 1024 + u;
    float* orow = out + (size_t)b * T_ * U_ + u;

    ScanBuf bufA, bufB;
    scan_load(bufA, gq, 0);

    #pragma unroll 1
    for (int t0 = 0; t0 < T_; t0 += 32) {
        scan_load(bufB, gq, (t0 >> 3) + 2);
        scan_compute(bufA, c, vr, vf, orow, t0);
        if (t0 + 32 < T_) scan_load(bufA, gq, (t0 >> 3) + 4);
        scan_compute(bufB, c, vr, vf, orow, t0 + 16);
    }
}

// ---------------------------------------------------------------------------
// Host launch.  Inputs: x, h0, c0, W, b, Vr, Vf
// ---------------------------------------------------------------------------
extern "C" void kernel_launch(void* const* d_in, const int* in_sizes, int n_in,
                              void* d_out, int out_size) {
    const float* x  = (const float*)d_in[0];
    // d_in[1] = h0 (unused by reference)
    const float* c0 = (const float*)d_in[2];
    const float* W  = (const float*)d_in[3];
    const float* b  = (const float*)d_in[4];
    const float* Vr = (const float*)d_in[5];
    const float* Vf = (const float*)d_in[6];
    float* out = (float*)d_out;

    void *pAh, *pBh;
    cudaGetSymbolAddress(&pAh, A_h_g);
    cudaGetSymbolAddress(&pBh, Wt_h_g);

    cudaFuncSetAttribute(sru_gemm_mma_kernel,
                         cudaFuncAttributeMaxDynamicSharedMemorySize, GEMM_SMEM);

    // Prep: round x to fp16, transpose+round W
    split_x_kernel<<<(int)((size_t)M_ * K_ / 4 / 256), 256>>>(x);
    transpose_w_kernel<<<dim3(N_ / 32, K_ / 32), dim3(32, 32)>>>(W);

    // Single-pass fp16 HMMA GEMM
    dim3 gg(N_ / BN, M_ / BM);  // (16, 256)
    sru_gemm_mma_kernel<<<gg, 256, GEMM_SMEM>>>(
        (const __half*)pAh, (const __half*)pBh, b);

    // Scan (vectorized loads over scan-friendly layout)
    sru_scan_kernel<<<(B_ * U_) / 256, 256>>>(c0, Vr, Vf, out);
}